// round 14
// baseline (speedup 1.0000x reference)
#include <cuda_runtime.h>
#include <cuda_fp16.h>

// ---------------- problem constants ----------------
#define Bv 16
#define Cv 64
#define Nv 4096
#define Mv 1024
#define LN2R 1.4426950408889634f

typedef unsigned long long ULL;

// ---------------- helpers ----------------
__device__ __forceinline__ ULL f2_fma(ULL a, ULL b, ULL c) {
    ULL d; asm("fma.rn.f32x2 %0, %1, %2, %3;" : "=l"(d) : "l"(a), "l"(b), "l"(c)); return d;
}
__device__ __forceinline__ ULL f2_pack(float lo, float hi) {
    ULL r;
    asm("mov.b64 %0, {%1, %2};" : "=l"(r)
        : "r"(__float_as_uint(lo)), "r"(__float_as_uint(hi)));
    return r;
}
__device__ __forceinline__ float2 f2_unpack(ULL v) {
    unsigned lo, hi;
    asm("mov.b64 {%0, %1}, %2;" : "=r"(lo), "=r"(hi) : "l"(v));
    return make_float2(__uint_as_float(lo), __uint_as_float(hi));
}
__device__ __forceinline__ float tf32r(float x) {
    float r; asm("cvt.rna.tf32.f32 %0, %1;" : "=f"(r) : "f"(x)); return r;
}
__device__ __forceinline__ unsigned cvt_f16x2(float hi, float lo) {
    unsigned r;
    asm("cvt.rn.f16x2.f32 %0, %1, %2;" : "=r"(r) : "f"(hi), "f"(lo));
    return r;
}
__device__ __forceinline__ unsigned ex2_f16x2(unsigned v) {
    unsigned r; asm("ex2.approx.f16x2 %0, %1;" : "=r"(r) : "r"(v)); return r;
}
__device__ __forceinline__ unsigned smem_u32(const void* p) {
    unsigned a;
    asm("{.reg .u64 t; cvta.to.shared.u64 t, %1; cvt.u32.u64 %0, t;}"
        : "=r"(a) : "l"(p));
    return a;
}
__device__ __forceinline__ void cpa16(unsigned dst, const void* src) {
    asm volatile("cp.async.cg.shared.global [%0], [%1], 16;"
                 :: "r"(dst), "l"(src));
}
#define CPA_COMMIT() asm volatile("cp.async.commit_group;" ::: "memory")
#define CPA_WAIT0()  asm volatile("cp.async.wait_group 0;" ::: "memory")

#define LDSM4(r, a) \
    asm volatile("ldmatrix.sync.aligned.m8n8.x4.shared.b16 {%0,%1,%2,%3},[%4];" \
        : "=r"((r)[0]), "=r"((r)[1]), "=r"((r)[2]), "=r"((r)[3]) : "r"(a))

// mma.sync m16n8k8 tf32
__device__ __forceinline__ void mma_qk(float d[4], const unsigned a[4],
                                       unsigned b0, unsigned b1) {
    asm("mma.sync.aligned.m16n8k8.row.col.f32.tf32.tf32.f32 "
        "{%0,%1,%2,%3},{%4,%5,%6,%7},{%8,%9},{%10,%11,%12,%13};"
        : "=f"(d[0]), "=f"(d[1]), "=f"(d[2]), "=f"(d[3])
        : "r"(a[0]), "r"(a[1]), "r"(a[2]), "r"(a[3]),
          "r"(b0), "r"(b1), "f"(0.f), "f"(0.f), "f"(0.f), "f"(0.f));
}
// mma.sync m16n8k16 f16 (accumulate in place, f32 accum)
__device__ __forceinline__ void mma_pv(float d[4], const unsigned a[4],
                                       unsigned b0, unsigned b1) {
    asm("mma.sync.aligned.m16n8k16.row.col.f32.f16.f16.f32 "
        "{%0,%1,%2,%3},{%4,%5,%6,%7},{%8,%9},{%0,%1,%2,%3};"
        : "+f"(d[0]), "+f"(d[1]), "+f"(d[2]), "+f"(d[3])
        : "r"(a[0]), "r"(a[1]), "r"(a[2]), "r"(a[3]), "r"(b0), "r"(b1));
}

// ---------------- scratch ----------------
__device__ float d_theta[Bv * Nv * 8];        // [b][n][k] tf32-rounded, *LN2R
__device__ float d_phi  [Bv * Mv * 8];        // [b][m][pairs (p,p+4)] tf32-rounded
__device__ __half d_gTh [Bv * 32 * Mv];       // [b][j][m] f16
__device__ float d_partO[2 * Bv * Nv * 32];   // split-K partial O
__device__ float d_partL[2 * Bv * Nv];        // split-K partial lsum
__device__ int   d_cnt  [Bv * 32];            // per (b, qblk) arrival counter

// ======================================================================
// prep_kernel (fused, single pass over x): grid (8, B), 256 threads.
// Also zeroes the split-K counters for this launch.
// ======================================================================
__global__ void __launch_bounds__(256)
prep_kernel(const float* __restrict__ x,
            const float* __restrict__ Wth,
            const float* __restrict__ Wphi,
            const float* __restrict__ Wg) {
    __shared__ float Wt[64 * 48];        // [c][0:8)=theta [8:16)=phi [16:48)=g
    __shared__ float red[128 * 41];

    int tid = threadIdx.x;
    int b = blockIdx.y;

    if (blockIdx.x == 0 && tid < 32) d_cnt[b * 32 + tid] = 0;

    for (int i = tid; i < 512; i += 256) {
        int k = i >> 6, c = i & 63;
        Wt[c * 48 + k] = Wth[i];
        Wt[c * 48 + 8 + k] = Wphi[i];
    }
    for (int i = tid; i < 2048; i += 256) {
        int j = i >> 6, c = i & 63;
        Wt[c * 48 + 16 + j] = Wg[i];
    }
    __syncthreads();

    int lm = tid & 127, half = tid >> 7;
    int m = blockIdx.x * 128 + lm;
    int h2 = m >> 5, w2 = m & 31;
    int n0 = ((h2 << 1) + half) * 64 + (w2 << 1);
    const float* xb = x + ((size_t)b * Cv) * Nv + n0;

    ULL acc0[24], acc1[24];
#pragma unroll
    for (int i = 0; i < 24; i++) { acc0[i] = 0ULL; acc1[i] = 0ULL; }

#pragma unroll 8
    for (int c = 0; c < 64; c++) {
        float2 xv = *(const float2*)(xb + (size_t)c * Nv);
        ULL xx0 = f2_pack(xv.x, xv.x);
        ULL xx1 = f2_pack(xv.y, xv.y);
        const ulonglong2* wr = (const ulonglong2*)&Wt[c * 48];
#pragma unroll
        for (int i = 0; i < 12; i++) {
            ulonglong2 wv = wr[i];
            acc0[2 * i]     = f2_fma(wv.x, xx0, acc0[2 * i]);
            acc0[2 * i + 1] = f2_fma(wv.y, xx0, acc0[2 * i + 1]);
            acc1[2 * i]     = f2_fma(wv.x, xx1, acc1[2 * i]);
            acc1[2 * i + 1] = f2_fma(wv.y, xx1, acc1[2 * i + 1]);
        }
    }

    {
        float t0[8], t1[8];
#pragma unroll
        for (int i = 0; i < 4; i++) {
            float2 v0 = f2_unpack(acc0[i]);
            float2 v1 = f2_unpack(acc1[i]);
            t0[2 * i] = v0.x; t0[2 * i + 1] = v0.y;
            t1[2 * i] = v1.x; t1[2 * i + 1] = v1.y;
        }
        float* d0 = d_theta + ((size_t)(b * Nv + n0)) * 8;
        ((float4*)d0)[0] = make_float4(tf32r(t0[0] * LN2R), tf32r(t0[1] * LN2R),
                                       tf32r(t0[2] * LN2R), tf32r(t0[3] * LN2R));
        ((float4*)d0)[1] = make_float4(tf32r(t0[4] * LN2R), tf32r(t0[5] * LN2R),
                                       tf32r(t0[6] * LN2R), tf32r(t0[7] * LN2R));
        float* d1 = d_theta + ((size_t)(b * Nv + n0 + 1)) * 8;
        ((float4*)d1)[0] = make_float4(tf32r(t1[0] * LN2R), tf32r(t1[1] * LN2R),
                                       tf32r(t1[2] * LN2R), tf32r(t1[3] * LN2R));
        ((float4*)d1)[1] = make_float4(tf32r(t1[4] * LN2R), tf32r(t1[5] * LN2R),
                                       tf32r(t1[6] * LN2R), tf32r(t1[7] * LN2R));
    }

    float bp[8], bg[32];
#pragma unroll
    for (int i = 0; i < 4; i++) {
        float2 v0 = f2_unpack(acc0[4 + i]);
        float2 v1 = f2_unpack(acc1[4 + i]);
        bp[2 * i] = fmaxf(v0.x, v1.x);
        bp[2 * i + 1] = fmaxf(v0.y, v1.y);
    }
#pragma unroll
    for (int i = 0; i < 16; i++) {
        float2 v0 = f2_unpack(acc0[8 + i]);
        float2 v1 = f2_unpack(acc1[8 + i]);
        bg[2 * i] = fmaxf(v0.x, v1.x);
        bg[2 * i + 1] = fmaxf(v0.y, v1.y);
    }

    if (half) {
        float* r = red + lm * 41;
#pragma unroll
        for (int k = 0; k < 8; k++) r[k] = bp[k];
#pragma unroll
        for (int j = 0; j < 32; j++) r[8 + j] = bg[j];
    }
    __syncthreads();
    if (!half) {
        const float* r = red + lm * 41;
#pragma unroll
        for (int k = 0; k < 8; k++) bp[k] = fmaxf(bp[k], r[k]);
#pragma unroll
        for (int j = 0; j < 32; j++) bg[j] = fmaxf(bg[j], r[8 + j]);

        float* pd = d_phi + ((size_t)(b * Mv + m)) * 8;
        ((float4*)pd)[0] = make_float4(tf32r(bp[0]), tf32r(bp[4]),
                                       tf32r(bp[1]), tf32r(bp[5]));
        ((float4*)pd)[1] = make_float4(tf32r(bp[2]), tf32r(bp[6]),
                                       tf32r(bp[3]), tf32r(bp[7]));
#pragma unroll
        for (int j = 0; j < 32; j++)
            d_gTh[((size_t)(b * 32 + j)) * Mv + m] = __float2half(bg[j]);
    }
}

// ======================================================================
// attn_kernel: split-K. grid (32, B, 2). 128 thr = 4 warps x 32q.
// Each CTA covers 512 keys (4 tiles). Both halves write partial O/lsum;
// second arrival (ticket) combines and runs the epilogue.
// ======================================================================
#define GT_PITCH 136
#define ONES_F16X2 0x3C003C00u

__global__ void __launch_bounds__(128, 5)
attn_kernel(const float* __restrict__ x,
            const float* __restrict__ Wattn,
            const float* __restrict__ sigma,
            float* __restrict__ out) {
    __shared__ __align__(16) char smraw[25600];
    __shared__ int s_old;
    unsigned sbase = smem_u32(smraw);

    int tid = threadIdx.x;
    int w = tid >> 5, l = tid & 31;
    int g = l >> 2, k4 = l & 3;
    int b = blockIdx.y;
    int s = blockIdx.z;
    int qbase = blockIdx.x * 128;

    unsigned aA[4], aB[4];
    {
        const float* th = d_theta + ((size_t)(b * Nv + qbase + w * 32)) * 8;
        aA[0] = __float_as_uint(th[g * 8 + k4]);
        aA[1] = __float_as_uint(th[(g + 8) * 8 + k4]);
        aA[2] = __float_as_uint(th[g * 8 + k4 + 4]);
        aA[3] = __float_as_uint(th[(g + 8) * 8 + k4 + 4]);
        const float* tb = th + 128;
        aB[0] = __float_as_uint(tb[g * 8 + k4]);
        aB[1] = __float_as_uint(tb[(g + 8) * 8 + k4]);
        aB[2] = __float_as_uint(tb[g * 8 + k4 + 4]);
        aB[3] = __float_as_uint(tb[(g + 8) * 8 + k4 + 4]);
    }

    float oA[4][4], oB[4][4];
#pragma unroll
    for (int jt = 0; jt < 4; jt++)
#pragma unroll
        for (int i = 0; i < 4; i++) { oA[jt][i] = 0.f; oB[jt][i] = 0.f; }
    float oSA[4] = {0.f, 0.f, 0.f, 0.f};
    float oSB[4] = {0.f, 0.f, 0.f, 0.f};

    const char* phi_g = (const char*)(d_phi + (size_t)b * (Mv * 8))
                        + (size_t)s * 4 * 4096;
    const char* gt_g = (const char*)(d_gTh + (size_t)b * (32 * Mv))
                       + (size_t)s * 4 * 256;

    // stage tile 0 into buffer 0
    {
        cpa16(sbase + tid * 16, phi_g + tid * 16);
        cpa16(sbase + (tid + 128) * 16, phi_g + (size_t)(tid + 128) * 16);
#pragma unroll
        for (int r = 0; r < 4; r++) {
            int i = tid + 128 * r;
            int row = i >> 4, c = i & 15;
            cpa16(sbase + 8192 + row * 272 + c * 16,
                  gt_g + (size_t)row * (Mv * 2) + c * 16);
        }
        CPA_COMMIT();
    }

#pragma unroll 1
    for (int mt = 0; mt < 4; mt++) {
        CPA_WAIT0();
        __syncthreads();

        int buf = mt & 1;
        if (mt < 3) {
            int nb = buf ^ 1;
            unsigned pbase = sbase + nb * 4096;
            unsigned gbase = sbase + 8192 + nb * 8704;
            const char* psrc = phi_g + (size_t)(mt + 1) * 4096;
            const char* gsrc = gt_g + (size_t)(mt + 1) * 256;
            cpa16(pbase + tid * 16, psrc + tid * 16);
            cpa16(pbase + (tid + 128) * 16, psrc + (size_t)(tid + 128) * 16);
#pragma unroll
            for (int r = 0; r < 4; r++) {
                int i = tid + 128 * r;
                int row = i >> 4, c = i & 15;
                cpa16(gbase + row * 272 + c * 16,
                      gsrc + (size_t)row * (Mv * 2) + c * 16);
            }
            CPA_COMMIT();
        }

        const float* phi_b = (const float*)(smraw + buf * 4096);
        unsigned gt_lane = sbase + 8192 + buf * 8704 + (unsigned)l * 272;

#pragma unroll
        for (int ms = 0; ms < 8; ms++) {
            int m0 = ms * 16;
            unsigned bg0[4], bg1[4];
            LDSM4(bg0, gt_lane + ms * 32);
            LDSM4(bg1, gt_lane + ms * 32 + 16);

            float2 bb0 = *(const float2*)&phi_b[(m0 + g) * 8 + k4 * 2];
            float2 bb1 = *(const float2*)&phi_b[(m0 + 8 + g) * 8 + k4 * 2];
            unsigned u0 = __float_as_uint(bb0.x), u1 = __float_as_uint(bb0.y);
            unsigned u2 = __float_as_uint(bb1.x), u3 = __float_as_uint(bb1.y);

            float sA0[4], sA1[4], sB0[4], sB1[4];
            mma_qk(sA0, aA, u0, u1);
            mma_qk(sA1, aA, u2, u3);
            mma_qk(sB0, aB, u0, u1);
            mma_qk(sB1, aB, u2, u3);

            unsigned paA[4], paB[4];
            paA[0] = ex2_f16x2(cvt_f16x2(sA0[1], sA0[0]));
            paA[1] = ex2_f16x2(cvt_f16x2(sA0[3], sA0[2]));
            paA[2] = ex2_f16x2(cvt_f16x2(sA1[1], sA1[0]));
            paA[3] = ex2_f16x2(cvt_f16x2(sA1[3], sA1[2]));
            paB[0] = ex2_f16x2(cvt_f16x2(sB0[1], sB0[0]));
            paB[1] = ex2_f16x2(cvt_f16x2(sB0[3], sB0[2]));
            paB[2] = ex2_f16x2(cvt_f16x2(sB1[1], sB1[0]));
            paB[3] = ex2_f16x2(cvt_f16x2(sB1[3], sB1[2]));

#pragma unroll
            for (int jt = 0; jt < 4; jt++) {
                mma_pv(oA[jt], paA, bg0[jt], bg1[jt]);
                mma_pv(oB[jt], paB, bg0[jt], bg1[jt]);
            }
            mma_pv(oSA, paA, ONES_F16X2, ONES_F16X2);
            mma_pv(oSB, paB, ONES_F16X2, ONES_F16X2);
        }
    }

    // ---- write partial O + lsum to gmem (fragment scatter) ----
    {
        float* po = d_partO + (((size_t)(s * Bv + b) * Nv + qbase + w * 32) * 32);
#pragma unroll
        for (int jt = 0; jt < 4; jt++) {
            int jc = jt * 8 + 2 * k4;
            *(float2*)&po[(g) * 32 + jc]      = make_float2(oA[jt][0], oA[jt][1]);
            *(float2*)&po[(g + 8) * 32 + jc]  = make_float2(oA[jt][2], oA[jt][3]);
            *(float2*)&po[(16 + g) * 32 + jc] = make_float2(oB[jt][0], oB[jt][1]);
            *(float2*)&po[(24 + g) * 32 + jc] = make_float2(oB[jt][2], oB[jt][3]);
        }
        if (k4 == 0) {
            float* pl = d_partL + ((size_t)(s * Bv + b) * Nv + qbase + w * 32);
            pl[g] = oSA[0]; pl[g + 8] = oSA[2];
            pl[16 + g] = oSB[0]; pl[24 + g] = oSB[2];
        }
    }
    __threadfence();
    if (tid == 0) s_old = atomicAdd(&d_cnt[b * 32 + blockIdx.x], 1);
    __syncthreads();
    if (s_old == 0) return;   // first arrival: partner will combine

    // ---- combine + epilogue (second arrival) ----
    float* o_s = (float*)smraw;                 // [128][32]
    float* wa_s = (float*)(smraw + 16384);      // [2048]
    float* lsum_s = (float*)(smraw + 24576);    // [128]

    if (k4 == 0) {
        lsum_s[w * 32 + g] = oSA[0];
        lsum_s[w * 32 + g + 8] = oSA[2];
        lsum_s[w * 32 + 16 + g] = oSB[0];
        lsum_s[w * 32 + 24 + g] = oSB[2];
    }
    {
        int q0 = w * 32;
#pragma unroll
        for (int jt = 0; jt < 4; jt++) {
            int jc = jt * 8 + 2 * k4;
            *(float2*)&o_s[(q0 + g) * 32 + jc] = make_float2(oA[jt][0], oA[jt][1]);
            *(float2*)&o_s[(q0 + g + 8) * 32 + jc] = make_float2(oA[jt][2], oA[jt][3]);
            *(float2*)&o_s[(q0 + 16 + g) * 32 + jc] = make_float2(oB[jt][0], oB[jt][1]);
            *(float2*)&o_s[(q0 + 24 + g) * 32 + jc] = make_float2(oB[jt][2], oB[jt][3]);
        }
    }
    for (int i = tid; i < 2048; i += 128) wa_s[i] = Wattn[i];
    __syncthreads();

    int q = tid;
    int sp = s ^ 1;
    const float* ppo = d_partO + (((size_t)(sp * Bv + b) * Nv + qbase + q) * 32);
    float lsum = lsum_s[q] +
                 __ldcg(d_partL + ((size_t)(sp * Bv + b) * Nv + qbase + q));
    float inv = sigma[0] / lsum;

    // build packed attended vector directly (no float staging array)
    ULL acc[16];
    {
        const float4* os = (const float4*)&o_s[q * 32];
#pragma unroll
        for (int i = 0; i < 8; i++) {
            float4 v = os[i];
            float4 p = __ldcg((const float4*)ppo + i);
            acc[2 * i]     = f2_pack((v.x + p.x) * inv, (v.y + p.y) * inv);
            acc[2 * i + 1] = f2_pack((v.z + p.z) * inv, (v.w + p.w) * inv);
        }
    }

    int n = qbase + q;
    const float* xp = x + ((size_t)b * Cv) * Nv + n;
    float* op = out + ((size_t)b * Cv) * Nv + n;
    const ulonglong2* wa_u = (const ulonglong2*)wa_s;
#pragma unroll 4
    for (int co = 0; co < 64; co++) {
        const ulonglong2* wr = wa_u + (size_t)co * 8;
        ULL d2 = 0ULL;
#pragma unroll
        for (int jj = 0; jj < 8; jj++) {
            ulonglong2 wv = wr[jj];
            d2 = f2_fma(acc[jj * 2 + 0], wv.x, d2);
            d2 = f2_fma(acc[jj * 2 + 1], wv.y, d2);
        }
        float2 df = f2_unpack(d2);
        op[(size_t)co * Nv] = xp[(size_t)co * Nv] + (df.x + df.y);
    }
}

// ======================================================================
// launch
// ======================================================================
extern "C" void kernel_launch(void* const* d_in, const int* in_sizes, int n_in,
                              void* d_out, int out_size) {
    const float* x     = (const float*)d_in[0];
    const float* Wth   = (const float*)d_in[1];
    const float* Wphi  = (const float*)d_in[2];
    const float* Wg    = (const float*)d_in[3];
    const float* Wattn = (const float*)d_in[4];
    const float* sigma = (const float*)d_in[5];
    float* out = (float*)d_out;

    prep_kernel<<<dim3(8, Bv), 256>>>(x, Wth, Wphi, Wg);
    attn_kernel<<<dim3(Nv / 128, Bv, 2), 128>>>(x, Wattn, sigma, out);
}